// round 1
// baseline (speedup 1.0000x reference)
#include <cuda_runtime.h>
#include <math.h>

#define LL   9216
#define DI   192
#define DS   16
#define DR   6
#define KK   4
#define XD   38
#define NB   2
#define NSEG 64
#define CH   144      // LL / NSEG
#define HH   96
#define WW   96
#define TLA  64
#define TLC  64

// ---------------- scratch (device globals; no allocation allowed) ----------------
__device__ float g_xi   [NB*LL*DI];          // in_proj x-part, pixel-major [b][l][d]
__device__ float g_z    [NB*LL*DI];          // gate z, pixel-major
__device__ float g_xc   [NB*LL*DI];          // conv+silu output, pixel-major
__device__ float g_delta[NB*KK*LL*DI];       // [b*K+k][scan l][d]
__device__ float g_bc   [NB*KK*LL*32];       // [b*K+k][scan l][B(16),C(16)]
__device__ float g_y    [NB*KK*LL*DI];       // scan output
__device__ float g_S    [NB*KK*NSEG*DS*DI];  // segment partial states [g][seg][n][d]
__device__ float g_dsm  [NB*KK*NSEG*DI];     // segment sum of delta  [g][seg][d]
__device__ float g_h0   [NB*KK*NSEG*DS*DI];  // segment initial states

__device__ __forceinline__ float softplusf_(float x){
    return fmaxf(x, 0.f) + log1pf(expf(-fabsf(x)));
}

// scan index i of direction k -> hw pixel index
__device__ __forceinline__ int pos_of(int k, int i){
    int t = (k >= 2) ? (LL - 1 - i) : i;
    if (k & 1){ int h = t % HH; int w = t / HH; return h*WW + w; }
    return t;
}

// ---------------- kernel A: in_proj (x[b,:,l] dot 384 rows) ----------------
__global__ void kA(const float* __restrict__ x, const float* __restrict__ w){
    extern __shared__ float s[];
    float* sw = s;               // [384][100] padded
    float* sx = sw + 384*100;    // [TLA][100] padded
    int tile = blockIdx.x;
    int b  = tile / (LL/TLA);
    int l0 = (tile % (LL/TLA)) * TLA;

    for (int i = threadIdx.x; i < 384*96; i += blockDim.x){
        int o = i/96, e = i%96; sw[o*100 + e] = w[i];
    }
    for (int i = threadIdx.x; i < 96*TLA; i += blockDim.x){
        int e = i / TLA, j = i % TLA;
        sx[j*100 + e] = x[(b*96 + e)*LL + l0 + j];
    }
    __syncthreads();

    for (int o = threadIdx.x; o < 384*TLA; o += blockDim.x){
        int out = o % 384, j = o / 384;     // consecutive threads: out consecutive -> coalesced writes
        const float4* wr = (const float4*)(sw + out*100);
        const float4* xr = (const float4*)(sx + j*100);
        float acc = 0.f;
        #pragma unroll
        for (int e = 0; e < 24; e++){
            float4 a = wr[e], c = xr[e];
            acc += a.x*c.x + a.y*c.y + a.z*c.z + a.w*c.w;
        }
        int base = (b*LL + l0 + j)*DI;
        if (out < DI) g_xi[base + out]      = acc;
        else          g_z [base + out - DI] = acc;
    }
}

// ---------------- kernel B: depthwise 3x3 conv + SiLU ----------------
__global__ void kB(const float* __restrict__ cw, const float* __restrict__ cb){
    __shared__ float scw[DI*9];
    __shared__ float scb[DI];
    for (int i = threadIdx.x; i < DI*9; i += blockDim.x) scw[i] = cw[i];
    for (int i = threadIdx.x; i < DI;   i += blockDim.x) scb[i] = cb[i];
    __syncthreads();
    int idx = blockIdx.x*blockDim.x + threadIdx.x;
    if (idx >= NB*LL*DI) return;
    int d = idx % DI; int l = (idx/DI) % LL; int b = idx/(DI*LL);
    int h = l / WW, w = l % WW;
    float acc = scb[d];
    #pragma unroll
    for (int ky = 0; ky < 3; ky++){
        int hh = h + ky - 1; if (hh < 0 || hh >= HH) continue;
        #pragma unroll
        for (int kx = 0; kx < 3; kx++){
            int w2 = w + kx - 1; if (w2 < 0 || w2 >= WW) continue;
            acc += scw[d*9 + ky*3 + kx] * g_xi[(b*LL + hh*WW + w2)*DI + d];
        }
    }
    g_xc[idx] = acc * (1.f / (1.f + __expf(-acc)));   // SiLU
}

// ---------------- kernel C1: x_proj + dt proj + softplus (fused) ----------------
__global__ void kC1(const float* __restrict__ xpw, const float* __restrict__ dtw,
                    const float* __restrict__ dtb){
    extern __shared__ float s[];
    float* swp = s;                     // [38][192]
    float* sdw = swp + XD*DI;           // [192][6]
    float* sdb = sdw + DI*DR;           // [192]
    float* sxs = sdb + DI;              // [TLC][196] padded
    float* sxd = sxs + TLC*196;         // [TLC][40]  padded
    int tile   = blockIdx.x;
    int ntile  = LL / TLC;
    int g  = tile / ntile;              // b*K + k
    int i0 = (tile % ntile) * TLC;
    int b = g / KK, k = g % KK;

    for (int i = threadIdx.x; i < XD*DI; i += blockDim.x) swp[i] = xpw[k*XD*DI + i];
    for (int i = threadIdx.x; i < DI*DR; i += blockDim.x) sdw[i] = dtw[k*DI*DR + i];
    for (int i = threadIdx.x; i < DI;    i += blockDim.x) sdb[i] = dtb[k*DI + i];
    for (int i = threadIdx.x; i < TLC*DI; i += blockDim.x){
        int j = i / DI, d = i % DI;
        sxs[j*196 + d] = g_xc[(b*LL + pos_of(k, i0 + j))*DI + d];
    }
    __syncthreads();

    // x_dbl[j][c] = sum_e xs[j][e] * W[c][e]
    for (int o = threadIdx.x; o < XD*TLC; o += blockDim.x){
        int c = o >> 6, j = o & 63;
        const float4* wr = (const float4*)(swp + c*DI);
        const float4* xr = (const float4*)(sxs + j*196);
        float acc = 0.f;
        #pragma unroll
        for (int e = 0; e < 48; e++){
            float4 a = wr[e], v = xr[e];
            acc += a.x*v.x + a.y*v.y + a.z*v.z + a.w*v.w;
        }
        sxd[j*40 + c] = acc;
    }
    __syncthreads();

    // write B,C rows
    for (int o = threadIdx.x; o < TLC*32; o += blockDim.x){
        int j = o >> 5, c = o & 31;
        g_bc[(g*LL + i0 + j)*32 + c] = sxd[j*40 + 6 + c];
    }
    // delta = softplus(x_dbl[0:6] @ dt_w^T + dt_b)
    for (int o = threadIdx.x; o < TLC*DI; o += blockDim.x){
        int j = o / DI, d = o % DI;
        const float* xd = sxd + j*40;
        const float* dw = sdw + d*DR;
        float acc = sdb[d];
        #pragma unroll
        for (int r = 0; r < DR; r++) acc += xd[r]*dw[r];
        g_delta[(g*LL + i0 + j)*DI + d] = softplusf_(acc);
    }
}

// ---------------- kernel D1: per-segment partial scan (h0 = 0, no y) ----------------
__global__ void __launch_bounds__(192) kD1(const float* __restrict__ A_logs){
    __shared__ float sB[CH*DS];
    int g   = blockIdx.x / NSEG;
    int seg = blockIdx.x % NSEG;
    int b = g / KK, k = g % KK;
    int d = threadIdx.x;
    int l0 = seg * CH;

    for (int i = threadIdx.x; i < CH*DS; i += blockDim.x){
        int ss = i >> 4, c = i & 15;
        sB[i] = g_bc[(g*LL + l0 + ss)*32 + c];
    }
    __syncthreads();

    float Ar[DS];
    const float* arow = A_logs + (k*DI + d)*DS;
    #pragma unroll
    for (int n = 0; n < DS; n++) Ar[n] = -expf(arow[n]);
    bool fast = true;
    #pragma unroll
    for (int n = 1; n < DS; n++)
        fast = fast && (fabsf(Ar[n] - (n+1)*Ar[0]) <= 1e-5f*fabsf(Ar[n]) + 1e-7f);

    float h[DS];
    #pragma unroll
    for (int n = 0; n < DS; n++) h[n] = 0.f;
    float dsum = 0.f;
    const float* dptr = g_delta + (g*LL + l0)*DI + d;

    if (fast){
        for (int s2 = 0; s2 < CH; s2++){
            int l = l0 + s2;
            float delta = dptr[s2*DI];
            float u = g_xc[(b*LL + pos_of(k, l))*DI + d];
            dsum += delta;
            float du = delta*u;
            float e1 = __expf(delta*Ar[0]);
            float e = e1;
            const float* Bp = sB + s2*DS;
            #pragma unroll
            for (int n = 0; n < DS; n++){
                h[n] = e*h[n] + du*Bp[n];
                e *= e1;
            }
        }
    } else {
        for (int s2 = 0; s2 < CH; s2++){
            int l = l0 + s2;
            float delta = dptr[s2*DI];
            float u = g_xc[(b*LL + pos_of(k, l))*DI + d];
            dsum += delta;
            float du = delta*u;
            const float* Bp = sB + s2*DS;
            #pragma unroll
            for (int n = 0; n < DS; n++){
                float e = __expf(delta*Ar[n]);
                h[n] = e*h[n] + du*Bp[n];
            }
        }
    }
    int sbase = ((g*NSEG + seg)*DS)*DI + d;
    #pragma unroll
    for (int n = 0; n < DS; n++) g_S[sbase + n*DI] = h[n];
    g_dsm[(g*NSEG + seg)*DI + d] = dsum;
}

// ---------------- kernel D2: stitch segment boundaries ----------------
__global__ void kD2(const float* __restrict__ A_logs){
    int t = blockIdx.x*blockDim.x + threadIdx.x;
    if (t >= NB*KK*DS*DI) return;
    int d = t % DI; int n = (t/DI) % DS; int g = t/(DI*DS);
    int k = g % KK;
    float An = -expf(A_logs[(k*DI + d)*DS + n]);
    float h = 0.f;
    for (int seg = 0; seg < NSEG; seg++){
        int base = g*NSEG + seg;
        g_h0[(base*DS + n)*DI + d] = h;
        float P = __expf(An * g_dsm[base*DI + d]);
        h = P*h + g_S[(base*DS + n)*DI + d];
    }
}

// ---------------- kernel D3: full scan with true h0, emit y ----------------
__global__ void __launch_bounds__(192) kD3(const float* __restrict__ A_logs,
                                           const float* __restrict__ Dsv){
    __shared__ float sBC[CH*32];
    int g   = blockIdx.x / NSEG;
    int seg = blockIdx.x % NSEG;
    int b = g / KK, k = g % KK;
    int d = threadIdx.x;
    int l0 = seg * CH;

    const float4* src = (const float4*)(g_bc + (size_t)(g*LL + l0)*32);
    float4* dst = (float4*)sBC;
    for (int i = threadIdx.x; i < CH*8; i += blockDim.x) dst[i] = src[i];
    __syncthreads();

    float Ar[DS];
    const float* arow = A_logs + (k*DI + d)*DS;
    #pragma unroll
    for (int n = 0; n < DS; n++) Ar[n] = -expf(arow[n]);
    bool fast = true;
    #pragma unroll
    for (int n = 1; n < DS; n++)
        fast = fast && (fabsf(Ar[n] - (n+1)*Ar[0]) <= 1e-5f*fabsf(Ar[n]) + 1e-7f);

    float h[DS];
    int hbase = ((g*NSEG + seg)*DS)*DI + d;
    #pragma unroll
    for (int n = 0; n < DS; n++) h[n] = g_h0[hbase + n*DI];
    float Dval = Dsv[k*DI + d];

    const float* dptr = g_delta + (g*LL + l0)*DI + d;
    float* yptr = g_y + (size_t)(g*LL + l0)*DI + d;

    if (fast){
        for (int s2 = 0; s2 < CH; s2++){
            int l = l0 + s2;
            float delta = dptr[s2*DI];
            float u = g_xc[(b*LL + pos_of(k, l))*DI + d];
            float du = delta*u;
            float e1 = __expf(delta*Ar[0]);
            float e = e1;
            const float* Bp = sBC + s2*32;
            const float* Cp = Bp + 16;
            float y = 0.f;
            #pragma unroll
            for (int n = 0; n < DS; n++){
                h[n] = e*h[n] + du*Bp[n];
                y += h[n]*Cp[n];
                e *= e1;
            }
            yptr[s2*DI] = y + Dval*u;
        }
    } else {
        for (int s2 = 0; s2 < CH; s2++){
            int l = l0 + s2;
            float delta = dptr[s2*DI];
            float u = g_xc[(b*LL + pos_of(k, l))*DI + d];
            float du = delta*u;
            const float* Bp = sBC + s2*32;
            const float* Cp = Bp + 16;
            float y = 0.f;
            #pragma unroll
            for (int n = 0; n < DS; n++){
                float e = __expf(delta*Ar[n]);
                h[n] = e*h[n] + du*Bp[n];
                y += h[n]*Cp[n];
            }
            yptr[s2*DI] = y + Dval*u;
        }
    }
}

// ---------------- kernel E: merge 4 dirs + LN + gate + out_proj + residual ----------------
__global__ void __launch_bounds__(192) kE(const float* __restrict__ opw,
                                          const float* __restrict__ lng,
                                          const float* __restrict__ lnb,
                                          const float* __restrict__ x,
                                          float* __restrict__ out){
    extern __shared__ float s[];
    float* sw    = s;              // [96][196] padded
    float* syo   = sw + 96*196;    // [192]
    float* spart = syo + DI;       // [2][96]
    float* sred  = spart + 192;    // [16]
    float* slg   = sred + 16;      // [192]
    float* slb   = slg + DI;       // [192]
    float* sout  = slb + DI;       // [96][64]

    int b  = blockIdx.x / (LL/64);
    int p0 = (blockIdx.x % (LL/64)) * 64;

    for (int i = threadIdx.x; i < 96*DI; i += blockDim.x){
        int c = i/DI, e = i%DI; sw[c*196 + e] = opw[i];
    }
    for (int i = threadIdx.x; i < DI; i += blockDim.x){ slg[i] = lng[i]; slb[i] = lnb[i]; }
    __syncthreads();

    int tid  = threadIdx.x;
    int lane = tid & 31, wrp = tid >> 5;

    for (int j = 0; j < 64; j++){
        int p = p0 + j;
        int h = p / WW, w = p % WW;
        int i1 = w*HH + h;
        int d = tid;
        float val = g_y[((size_t)(b*KK + 0)*LL + p)*DI + d]
                  + g_y[((size_t)(b*KK + 2)*LL + (LL-1-p))*DI + d]
                  + g_y[((size_t)(b*KK + 1)*LL + i1)*DI + d]
                  + g_y[((size_t)(b*KK + 3)*LL + (LL-1-i1))*DI + d];
        float s1 = val, s2 = val*val;
        #pragma unroll
        for (int off = 16; off; off >>= 1){
            s1 += __shfl_xor_sync(0xffffffffu, s1, off);
            s2 += __shfl_xor_sync(0xffffffffu, s2, off);
        }
        if (lane == 0){ sred[wrp] = s1; sred[8 + wrp] = s2; }
        __syncthreads();
        float su = 0.f, sq = 0.f;
        #pragma unroll
        for (int w2 = 0; w2 < 6; w2++){ su += sred[w2]; sq += sred[8 + w2]; }
        float mu  = su * (1.f/192.f);
        float var = sq * (1.f/192.f) - mu*mu;
        float inv = rsqrtf(var + 1e-5f);
        float yo  = (val - mu)*inv*slg[d] + slb[d];
        float zv  = g_z[((size_t)b*LL + p)*DI + d];
        yo *= zv * (1.f / (1.f + __expf(-zv)));
        syo[d] = yo;
        __syncthreads();
        {
            int c = tid % 96, half = tid / 96;
            const float4* wr = (const float4*)(sw + c*196 + half*96);
            const float4* yr = (const float4*)(syo + half*96);
            float acc = 0.f;
            #pragma unroll
            for (int e = 0; e < 24; e++){
                float4 a = wr[e], v = yr[e];
                acc += a.x*v.x + a.y*v.y + a.z*v.z + a.w*v.w;
            }
            spart[half*96 + c] = acc;
        }
        __syncthreads();
        if (tid < 96){
            float tot = spart[tid] + spart[96 + tid] + x[(b*96 + tid)*LL + p];
            sout[tid*64 + j] = tot;
        }
        __syncthreads();
    }
    for (int i = threadIdx.x; i < 96*64; i += blockDim.x){
        int c = i/64, j = i%64;
        out[(b*96 + c)*LL + p0 + j] = sout[i];
    }
}

// ---------------- launch ----------------
extern "C" void kernel_launch(void* const* d_in, const int* in_sizes, int n_in,
                              void* d_out, int out_size){
    const float* x    = (const float*)d_in[0];
    const float* ipw  = (const float*)d_in[1];
    const float* cw   = (const float*)d_in[2];
    const float* cb   = (const float*)d_in[3];
    const float* xpw  = (const float*)d_in[4];
    const float* dtw  = (const float*)d_in[5];
    const float* dtb  = (const float*)d_in[6];
    const float* alog = (const float*)d_in[7];
    const float* Dsv  = (const float*)d_in[8];
    const float* lng  = (const float*)d_in[9];
    const float* lnb  = (const float*)d_in[10];
    const float* opw  = (const float*)d_in[11];
    float* out = (float*)d_out;

    int smA = (384*100 + TLA*100) * 4;                       // 179200
    int smC = (XD*DI + DI*DR + DI + TLC*196 + TLC*40) * 4;   // 94976
    int smE = (96*196 + DI + 192 + 16 + DI + DI + 96*64) * 4; // 102976
    cudaFuncSetAttribute(kA,  cudaFuncAttributeMaxDynamicSharedMemorySize, smA);
    cudaFuncSetAttribute(kC1, cudaFuncAttributeMaxDynamicSharedMemorySize, smC);
    cudaFuncSetAttribute(kE,  cudaFuncAttributeMaxDynamicSharedMemorySize, smE);

    kA<<<NB*(LL/TLA), 512, smA>>>(x, ipw);
    kB<<<(NB*LL*DI + 255)/256, 256>>>(cw, cb);
    kC1<<<NB*KK*(LL/TLC), 256, smC>>>(xpw, dtw, dtb);
    kD1<<<NB*KK*NSEG, 192>>>(alog);
    kD2<<<(NB*KK*DS*DI + 255)/256, 256>>>(alog);
    kD3<<<NB*KK*NSEG, 192>>>(alog, Dsv);
    kE<<<NB*(LL/64), 192, smE>>>(opw, lng, lnb, x, out);
}

// round 2
// speedup vs baseline: 1.1996x; 1.1996x over previous
#include <cuda_runtime.h>
#include <math.h>

#define LL   9216
#define DI   192
#define DS   16
#define DR   6
#define KK   4
#define XD   38
#define NB   2
#define NSEG 192
#define CH   48       // LL / NSEG
#define HH   96
#define WW   96
#define TLA  64
#define TLC  128

// ---------------- scratch (device globals; no allocation allowed) ----------------
__device__ float g_xi   [NB*LL*DI];
__device__ float g_z    [NB*LL*DI];
__device__ float g_xc   [NB*LL*DI];
__device__ float g_delta[NB*KK*LL*DI];
__device__ float g_bc   [NB*KK*LL*32];
__device__ float g_y    [NB*KK*LL*DI];
__device__ float g_S    [NB*KK*NSEG*DS*DI];
__device__ float g_dsm  [NB*KK*NSEG*DI];
__device__ float g_h0   [NB*KK*NSEG*DS*DI];

__device__ __forceinline__ float softplusf_(float x){
    return fmaxf(x, 0.f) + log1pf(expf(-fabsf(x)));
}

__device__ __forceinline__ int pos_of(int k, int i){
    int t = (k >= 2) ? (LL - 1 - i) : i;
    if (k & 1){ int h = t % HH; int w = t / HH; return h*WW + w; }
    return t;
}

// ---------------- kernel A: in_proj, register-tiled 6x8 ----------------
__global__ void __launch_bounds__(512) kA(const float* __restrict__ x, const float* __restrict__ w){
    extern __shared__ float s[];
    float* sw = s;               // [384][100]
    float* sx = sw + 384*100;    // [64][100]; later reused as staging [8][385]
    int tid = threadIdx.x;
    int b  = blockIdx.x / (LL/TLA);
    int l0 = (blockIdx.x % (LL/TLA)) * TLA;

    for (int i = tid; i < 384*96; i += 512){
        int o = i/96, e = i%96; sw[o*100 + e] = w[i];
    }
    for (int i = tid; i < 96*TLA; i += 512){
        int e = i / TLA, j = i % TLA;
        sx[j*100 + e] = x[(b*96 + e)*LL + l0 + j];
    }
    __syncthreads();

    int ot = tid >> 3;         // 0..63 -> outs ot*6 .. ot*6+5
    int pt = tid & 7;          // px = pt + 8*j

    float acc[6][8];
    #pragma unroll
    for (int i = 0; i < 6; i++)
        #pragma unroll
        for (int j = 0; j < 8; j++) acc[i][j] = 0.f;

    for (int e = 0; e < 96; e += 4){
        float4 xv[8];
        #pragma unroll
        for (int j = 0; j < 8; j++) xv[j] = *(const float4*)(sx + (pt + 8*j)*100 + e);
        #pragma unroll
        for (int i = 0; i < 6; i++){
            float4 wv = *(const float4*)(sw + (ot*6 + i)*100 + e);
            #pragma unroll
            for (int j = 0; j < 8; j++){
                acc[i][j] += wv.x*xv[j].x + wv.y*xv[j].y + wv.z*xv[j].z + wv.w*xv[j].w;
            }
        }
    }

    // staged coalesced writes: round j covers pixels l0+8j .. l0+8j+7
    float* sbuf = sx;   // 8*385 floats
    for (int j = 0; j < 8; j++){
        __syncthreads();
        #pragma unroll
        for (int i = 0; i < 6; i++) sbuf[pt*385 + ot*6 + i] = acc[i][j];
        __syncthreads();
        int pbase = l0 + 8*j;
        for (int idx = tid; idx < 8*384; idx += 512){
            int pp = idx/384, o = idx%384;
            float v = sbuf[pp*385 + o];
            if (o < DI) g_xi[(b*LL + pbase + pp)*DI + o]      = v;
            else        g_z [(b*LL + pbase + pp)*DI + o - DI] = v;
        }
    }
}

// ---------------- kernel B: depthwise 3x3 conv + SiLU ----------------
__global__ void kB(const float* __restrict__ cw, const float* __restrict__ cb){
    __shared__ float scw[DI*9];
    __shared__ float scb[DI];
    for (int i = threadIdx.x; i < DI*9; i += blockDim.x) scw[i] = cw[i];
    for (int i = threadIdx.x; i < DI;   i += blockDim.x) scb[i] = cb[i];
    __syncthreads();
    int idx = blockIdx.x*blockDim.x + threadIdx.x;
    if (idx >= NB*LL*DI) return;
    int d = idx % DI; int l = (idx/DI) % LL; int b = idx/(DI*LL);
    int h = l / WW, w = l % WW;
    float acc = scb[d];
    #pragma unroll
    for (int ky = 0; ky < 3; ky++){
        int hh = h + ky - 1; if (hh < 0 || hh >= HH) continue;
        #pragma unroll
        for (int kx = 0; kx < 3; kx++){
            int w2 = w + kx - 1; if (w2 < 0 || w2 >= WW) continue;
            acc += scw[d*9 + ky*3 + kx] * g_xi[(b*LL + hh*WW + w2)*DI + d];
        }
    }
    g_xc[idx] = acc * (1.f / (1.f + __expf(-acc)));
}

// ---------------- kernel C1: x_proj + dt proj, register-tiled ----------------
__global__ void __launch_bounds__(320) kC1(const float* __restrict__ xpw, const float* __restrict__ dtw,
                    const float* __restrict__ dtb){
    extern __shared__ float s[];
    float* swp = s;                     // [40][192]  (rows 38,39 zero)
    float* sdw = swp + 40*DI;           // [192][6]
    float* sdb = sdw + DI*DR;           // [192]
    float* sxs = sdb + DI;              // [128][196]
    float* sxd = sxs + TLC*196;         // [128][40]
    int tid = threadIdx.x;
    int tile   = blockIdx.x;
    int ntile  = LL / TLC;
    int g  = tile / ntile;
    int i0 = (tile % ntile) * TLC;
    int b = g / KK, k = g % KK;

    for (int i = tid; i < 40*DI; i += 320)
        swp[i] = (i < XD*DI) ? xpw[k*XD*DI + i] : 0.f;
    for (int i = tid; i < DI*DR; i += 320) sdw[i] = dtw[k*DI*DR + i];
    for (int i = tid; i < DI;    i += 320) sdb[i] = dtb[k*DI + i];
    for (int i = tid; i < TLC*DI; i += 320){
        int j = i / DI, d = i % DI;
        sxs[j*196 + d] = g_xc[(b*LL + pos_of(k, i0 + j))*DI + d];
    }
    __syncthreads();

    // GEMM: 40 outs x 128 px x 192 k; thread = (ot 0..9)x(pt 0..31), microtile 4x4
    {
        int ot = tid >> 5;     // warp-uniform -> broadcast weight loads
        int pt = tid & 31;     // px = pt + 32*j
        float acc[4][4];
        #pragma unroll
        for (int i = 0; i < 4; i++)
            #pragma unroll
            for (int j = 0; j < 4; j++) acc[i][j] = 0.f;
        for (int e = 0; e < DI; e += 4){
            float4 xv[4];
            #pragma unroll
            for (int j = 0; j < 4; j++) xv[j] = *(const float4*)(sxs + (pt + 32*j)*196 + e);
            #pragma unroll
            for (int i = 0; i < 4; i++){
                float4 wv = *(const float4*)(swp + (ot*4 + i)*DI + e);
                #pragma unroll
                for (int j = 0; j < 4; j++){
                    acc[i][j] += wv.x*xv[j].x + wv.y*xv[j].y + wv.z*xv[j].z + wv.w*xv[j].w;
                }
            }
        }
        #pragma unroll
        for (int i = 0; i < 4; i++)
            #pragma unroll
            for (int j = 0; j < 4; j++)
                sxd[(pt + 32*j)*40 + ot*4 + i] = acc[i][j];
    }
    __syncthreads();

    for (int o = tid; o < TLC*32; o += 320){
        int j = o >> 5, c = o & 31;
        g_bc[(g*LL + i0 + j)*32 + c] = sxd[j*40 + 6 + c];
    }
    for (int o = tid; o < TLC*DI; o += 320){
        int j = o / DI, d = o % DI;
        const float* xd = sxd + j*40;
        const float* dw = sdw + d*DR;
        float acc = sdb[d];
        #pragma unroll
        for (int r = 0; r < DR; r++) acc += xd[r]*dw[r];
        g_delta[(g*LL + i0 + j)*DI + d] = softplusf_(acc);
    }
}

// ---------------- kernel D1: per-segment partial scan (h0=0) ----------------
__global__ void __launch_bounds__(96) kD1(const float* __restrict__ A_logs){
    __shared__ float sB[CH*DS];
    int blk = blockIdx.x;
    int half = blk & 1;
    int gs  = blk >> 1;
    int g   = gs / NSEG;
    int seg = gs % NSEG;
    int b = g / KK, k = g % KK;
    int d = half*96 + threadIdx.x;
    int l0 = seg * CH;

    for (int i = threadIdx.x; i < CH*DS; i += 96){
        int ss = i >> 4, c = i & 15;
        sB[i] = g_bc[(g*LL + l0 + ss)*32 + c];
    }
    __syncthreads();

    const float* arow = A_logs + (k*DI + d)*DS;
    float a0 = arow[0];
    bool fast = true;
    #pragma unroll
    for (int n = 1; n < DS; n++){
        float an = arow[n];
        fast = fast && (fabsf(an - a0 - logf((float)(n+1))) <= 2e-5f);
    }
    float Ar0 = -expf(a0);

    float h[DS];
    #pragma unroll
    for (int n = 0; n < DS; n++) h[n] = 0.f;
    float dsum = 0.f;
    const float* dptr = g_delta + ((size_t)g*LL + l0)*DI + d;

    if (fast){
        float delta = dptr[0];
        float u = g_xc[(b*LL + pos_of(k, l0))*DI + d];
        for (int s2 = 0; s2 < CH; s2++){
            float nd = 0.f, nu = 0.f;
            if (s2 + 1 < CH){
                nd = dptr[(s2+1)*DI];
                nu = g_xc[(b*LL + pos_of(k, l0+s2+1))*DI + d];
            }
            dsum += delta;
            float du = delta*u;
            float e1 = __expf(delta*Ar0);
            const float4* Bp4 = (const float4*)(sB + s2*DS);
            float4 b0 = Bp4[0], b1 = Bp4[1], b2 = Bp4[2], b3 = Bp4[3];
            float e = e1;
            h[0]=e*h[0]+du*b0.x; e*=e1; h[1]=e*h[1]+du*b0.y; e*=e1;
            h[2]=e*h[2]+du*b0.z; e*=e1; h[3]=e*h[3]+du*b0.w; e*=e1;
            h[4]=e*h[4]+du*b1.x; e*=e1; h[5]=e*h[5]+du*b1.y; e*=e1;
            h[6]=e*h[6]+du*b1.z; e*=e1; h[7]=e*h[7]+du*b1.w; e*=e1;
            h[8]=e*h[8]+du*b2.x; e*=e1; h[9]=e*h[9]+du*b2.y; e*=e1;
            h[10]=e*h[10]+du*b2.z; e*=e1; h[11]=e*h[11]+du*b2.w; e*=e1;
            h[12]=e*h[12]+du*b3.x; e*=e1; h[13]=e*h[13]+du*b3.y; e*=e1;
            h[14]=e*h[14]+du*b3.z; e*=e1; h[15]=e*h[15]+du*b3.w;
            delta = nd; u = nu;
        }
    } else {
        for (int s2 = 0; s2 < CH; s2++){
            float delta = dptr[s2*DI];
            float u = g_xc[(b*LL + pos_of(k, l0+s2))*DI + d];
            dsum += delta;
            float du = delta*u;
            const float* Bp = sB + s2*DS;
            #pragma unroll
            for (int n = 0; n < DS; n++){
                float e = __expf(delta * (-expf(arow[n])));
                h[n] = e*h[n] + du*Bp[n];
            }
        }
    }
    size_t sbase = (((size_t)g*NSEG + seg)*DS)*DI + d;
    #pragma unroll
    for (int n = 0; n < DS; n++) g_S[sbase + n*DI] = h[n];
    g_dsm[((size_t)g*NSEG + seg)*DI + d] = dsum;
}

// ---------------- kernel D2: stitch segment boundaries ----------------
__global__ void kD2(const float* __restrict__ A_logs){
    int t = blockIdx.x*blockDim.x + threadIdx.x;
    if (t >= NB*KK*DS*DI) return;
    int d = t % DI; int n = (t/DI) % DS; int g = t/(DI*DS);
    int k = g % KK;
    float An = -expf(A_logs[(k*DI + d)*DS + n]);
    float h = 0.f;
    for (int seg = 0; seg < NSEG; seg++){
        size_t base = (size_t)g*NSEG + seg;
        g_h0[(base*DS + n)*DI + d] = h;
        float P = __expf(An * g_dsm[base*DI + d]);
        h = P*h + g_S[(base*DS + n)*DI + d];
    }
}

// ---------------- kernel D3: full scan with true h0, emit y ----------------
__global__ void __launch_bounds__(96) kD3(const float* __restrict__ A_logs,
                                          const float* __restrict__ Dsv){
    __shared__ float sBC[CH*32];
    int blk = blockIdx.x;
    int half = blk & 1;
    int gs  = blk >> 1;
    int g   = gs / NSEG;
    int seg = gs % NSEG;
    int b = g / KK, k = g % KK;
    int d = half*96 + threadIdx.x;
    int l0 = seg * CH;

    {
        const float4* src = (const float4*)(g_bc + ((size_t)g*LL + l0)*32);
        float4* dst = (float4*)sBC;
        for (int i = threadIdx.x; i < CH*8; i += 96) dst[i] = src[i];
    }
    __syncthreads();

    const float* arow = A_logs + (k*DI + d)*DS;
    float a0 = arow[0];
    bool fast = true;
    #pragma unroll
    for (int n = 1; n < DS; n++){
        float an = arow[n];
        fast = fast && (fabsf(an - a0 - logf((float)(n+1))) <= 2e-5f);
    }
    float Ar0 = -expf(a0);

    float h[DS];
    size_t hbase = (((size_t)g*NSEG + seg)*DS)*DI + d;
    #pragma unroll
    for (int n = 0; n < DS; n++) h[n] = g_h0[hbase + n*DI];
    float Dval = Dsv[k*DI + d];

    const float* dptr = g_delta + ((size_t)g*LL + l0)*DI + d;
    float* yptr = g_y + ((size_t)g*LL + l0)*DI + d;

    if (fast){
        float delta = dptr[0];
        float u = g_xc[(b*LL + pos_of(k, l0))*DI + d];
        for (int s2 = 0; s2 < CH; s2++){
            float nd = 0.f, nu = 0.f;
            if (s2 + 1 < CH){
                nd = dptr[(s2+1)*DI];
                nu = g_xc[(b*LL + pos_of(k, l0+s2+1))*DI + d];
            }
            float du = delta*u;
            float e1 = __expf(delta*Ar0);
            const float4* P4 = (const float4*)(sBC + s2*32);
            float4 b0 = P4[0], b1 = P4[1], b2 = P4[2], b3 = P4[3];
            float4 c0 = P4[4], c1 = P4[5], c2 = P4[6], c3 = P4[7];
            float e = e1;
            float y = 0.f;
            h[0]=e*h[0]+du*b0.x; y+=h[0]*c0.x; e*=e1;
            h[1]=e*h[1]+du*b0.y; y+=h[1]*c0.y; e*=e1;
            h[2]=e*h[2]+du*b0.z; y+=h[2]*c0.z; e*=e1;
            h[3]=e*h[3]+du*b0.w; y+=h[3]*c0.w; e*=e1;
            h[4]=e*h[4]+du*b1.x; y+=h[4]*c1.x; e*=e1;
            h[5]=e*h[5]+du*b1.y; y+=h[5]*c1.y; e*=e1;
            h[6]=e*h[6]+du*b1.z; y+=h[6]*c1.z; e*=e1;
            h[7]=e*h[7]+du*b1.w; y+=h[7]*c1.w; e*=e1;
            h[8]=e*h[8]+du*b2.x; y+=h[8]*c2.x; e*=e1;
            h[9]=e*h[9]+du*b2.y; y+=h[9]*c2.y; e*=e1;
            h[10]=e*h[10]+du*b2.z; y+=h[10]*c2.z; e*=e1;
            h[11]=e*h[11]+du*b2.w; y+=h[11]*c2.w; e*=e1;
            h[12]=e*h[12]+du*b3.x; y+=h[12]*c3.x; e*=e1;
            h[13]=e*h[13]+du*b3.y; y+=h[13]*c3.y; e*=e1;
            h[14]=e*h[14]+du*b3.z; y+=h[14]*c3.z; e*=e1;
            h[15]=e*h[15]+du*b3.w; y+=h[15]*c3.w;
            yptr[s2*DI] = y + Dval*u;
            delta = nd; u = nu;
        }
    } else {
        for (int s2 = 0; s2 < CH; s2++){
            float delta = dptr[s2*DI];
            float u = g_xc[(b*LL + pos_of(k, l0+s2))*DI + d];
            float du = delta*u;
            const float* Bp = sBC + s2*32;
            const float* Cp = Bp + 16;
            float y = 0.f;
            #pragma unroll
            for (int n = 0; n < DS; n++){
                float e = __expf(delta * (-expf(arow[n])));
                h[n] = e*h[n] + du*Bp[n];
                y += h[n]*Cp[n];
            }
            yptr[s2*DI] = y + Dval*u;
        }
    }
}

// ---------------- kernel E: merge + LN + gate + out_proj + residual ----------------
__global__ void __launch_bounds__(256) kE(const float* __restrict__ opw,
                                          const float* __restrict__ lng,
                                          const float* __restrict__ lnb,
                                          const float* __restrict__ x,
                                          float* __restrict__ out){
    extern __shared__ float s[];
    float* sw  = s;              // [96][196]
    float* syo = sw + 96*196;    // [64][196]; later reused as sout[96][64]
    float* slg = syo + 64*196;   // [192]
    float* slb = slg + DI;       // [192]

    int tid = threadIdx.x;
    int b  = blockIdx.x / (LL/64);
    int p0 = (blockIdx.x % (LL/64)) * 64;

    for (int i = tid; i < 96*DI; i += 256){
        int c = i/DI, e = i%DI; sw[c*196 + e] = opw[i];
    }
    for (int i = tid; i < DI; i += 256){ slg[i] = lng[i]; slb[i] = lnb[i]; }
    __syncthreads();

    int lane = tid & 31, wrp = tid >> 5;

    // phase 1: warp-per-pixel merged LN + gate (8 pixels per warp, serial)
    for (int jj = 0; jj < 8; jj++){
        int j = wrp*8 + jj;
        int p = p0 + j;
        int ph = p / WW, pw = p % WW;
        int i1 = pw*HH + ph;
        float val[6];
        #pragma unroll
        for (int i = 0; i < 6; i++){
            int d = lane + 32*i;
            val[i] = g_y[(((size_t)(b*KK + 0))*LL + p)*DI + d]
                   + g_y[(((size_t)(b*KK + 2))*LL + (LL-1-p))*DI + d]
                   + g_y[(((size_t)(b*KK + 1))*LL + i1)*DI + d]
                   + g_y[(((size_t)(b*KK + 3))*LL + (LL-1-i1))*DI + d];
        }
        float s1 = 0.f, s2 = 0.f;
        #pragma unroll
        for (int i = 0; i < 6; i++){ s1 += val[i]; s2 += val[i]*val[i]; }
        #pragma unroll
        for (int off = 16; off; off >>= 1){
            s1 += __shfl_xor_sync(0xffffffffu, s1, off);
            s2 += __shfl_xor_sync(0xffffffffu, s2, off);
        }
        float mu  = s1 * (1.f/192.f);
        float var = s2 * (1.f/192.f) - mu*mu;
        float inv = rsqrtf(var + 1e-5f);
        #pragma unroll
        for (int i = 0; i < 6; i++){
            int d = lane + 32*i;
            float yo = (val[i] - mu)*inv*slg[d] + slb[d];
            float zv = g_z[((size_t)b*LL + p)*DI + d];
            yo *= zv * (1.f / (1.f + __expf(-zv)));
            syo[j*196 + d] = yo;
        }
    }
    __syncthreads();

    // phase 2: GEMM 96 x 64 x 192, microtile 6x4
    int ct = tid >> 4;       // 0..15 -> outs ct*6..+5
    int pt = tid & 15;       // px = pt + 16*j
    float acc[6][4];
    #pragma unroll
    for (int i = 0; i < 6; i++)
        #pragma unroll
        for (int j = 0; j < 4; j++) acc[i][j] = 0.f;
    for (int e = 0; e < DI; e += 4){
        float4 xv[4];
        #pragma unroll
        for (int j = 0; j < 4; j++) xv[j] = *(const float4*)(syo + (pt + 16*j)*196 + e);
        #pragma unroll
        for (int i = 0; i < 6; i++){
            float4 wv = *(const float4*)(sw + (ct*6 + i)*196 + e);
            #pragma unroll
            for (int j = 0; j < 4; j++){
                acc[i][j] += wv.x*xv[j].x + wv.y*xv[j].y + wv.z*xv[j].z + wv.w*xv[j].w;
            }
        }
    }
    __syncthreads();
    // phase 3: stage + coalesced write with residual
    #pragma unroll
    for (int i = 0; i < 6; i++)
        #pragma unroll
        for (int j = 0; j < 4; j++)
            syo[(ct*6 + i)*64 + pt + 16*j] = acc[i][j];
    __syncthreads();
    for (int idx = tid; idx < 96*64; idx += 256){
        int c = idx >> 6, jx = idx & 63;
        size_t go = ((size_t)b*96 + c)*LL + p0 + jx;
        out[go] = syo[idx] + x[go];
    }
}

// ---------------- launch ----------------
extern "C" void kernel_launch(void* const* d_in, const int* in_sizes, int n_in,
                              void* d_out, int out_size){
    const float* x    = (const float*)d_in[0];
    const float* ipw  = (const float*)d_in[1];
    const float* cw   = (const float*)d_in[2];
    const float* cb   = (const float*)d_in[3];
    const float* xpw  = (const float*)d_in[4];
    const float* dtw  = (const float*)d_in[5];
    const float* dtb  = (const float*)d_in[6];
    const float* alog = (const float*)d_in[7];
    const float* Dsv  = (const float*)d_in[8];
    const float* lng  = (const float*)d_in[9];
    const float* lnb  = (const float*)d_in[10];
    const float* opw  = (const float*)d_in[11];
    float* out = (float*)d_out;

    int smA = (384*100 + 64*100) * 4;
    int smC = (40*DI + DI*DR + DI + TLC*196 + TLC*40) * 4;
    int smE = (96*196 + 64*196 + DI + DI) * 4;
    cudaFuncSetAttribute(kA,  cudaFuncAttributeMaxDynamicSharedMemorySize, smA);
    cudaFuncSetAttribute(kC1, cudaFuncAttributeMaxDynamicSharedMemorySize, smC);
    cudaFuncSetAttribute(kE,  cudaFuncAttributeMaxDynamicSharedMemorySize, smE);

    kA<<<NB*(LL/TLA), 512, smA>>>(x, ipw);
    kB<<<(NB*LL*DI + 255)/256, 256>>>(cw, cb);
    kC1<<<NB*KK*(LL/TLC), 320, smC>>>(xpw, dtw, dtb);
    kD1<<<NB*KK*NSEG*2, 96>>>(alog);
    kD2<<<(NB*KK*DS*DI + 255)/256, 256>>>(alog);
    kD3<<<NB*KK*NSEG*2, 96>>>(alog, Dsv);
    kE<<<NB*(LL/64), 256, smE>>>(opw, lng, lnb, x, out);
}